// round 2
// baseline (speedup 1.0000x reference)
#include <cuda_runtime.h>

#define B_TOK 1024
#define DDIM  768
#define FDIM  24576
#define KTOP  64
#define CONN  32

// ---------------- scratch (device globals: no allocation allowed) ----------------
__device__ float g_pre[(size_t)B_TOK * FDIM];        // reused for up then down
__device__ float g_WupT[(size_t)FDIM * DDIM];        // W_dec_up^T   [F, D]
__device__ float g_WdownT[(size_t)FDIM * DDIM];      // W_dec_down^T [F, D]
__device__ float g_upvals[B_TOK * KTOP];
__device__ int   g_upidx[B_TOK * KTOP];
__device__ float g_downvals[B_TOK * KTOP];
__device__ int   g_downidx[B_TOK * KTOP];
__device__ float g_approx[B_TOK * KTOP];

// ---------------- transpose W_dec [D, F] -> [F, D] ----------------
__global__ void transpose_kernel(const float* __restrict__ in, int which)
{
    __shared__ float tile[32][33];
    float* out = (which == 0) ? g_WupT : g_WdownT;
    int f0 = blockIdx.x * 32;
    int d0 = blockIdx.y * 32;
    int x = threadIdx.x, y = threadIdx.y;  // 32 x 8
#pragma unroll
    for (int j = 0; j < 32; j += 8)
        tile[y + j][x] = in[(size_t)(d0 + y + j) * FDIM + f0 + x];
    __syncthreads();
#pragma unroll
    for (int j = 0; j < 32; j += 8)
        out[(size_t)(f0 + y + j) * DDIM + d0 + x] = tile[x][y + j];
}

// ---------------- encode GEMM: pre = relu((X - b_dec) @ W^T + b_enc) ----------------
// X: [B, D] row-major, W: [F, D] row-major, pre: [B, F]
// 128x128 tile, BK=16, 256 threads, 8x8 per thread
__global__ __launch_bounds__(256, 2)
void encode_gemm_kernel(const float* __restrict__ X, const float* __restrict__ W,
                        const float* __restrict__ b_enc, const float* __restrict__ b_dec)
{
    __shared__ float As[16][128];
    __shared__ float Ws[16][128];
    const int bn = blockIdx.x * 128;   // over F
    const int bm = blockIdx.y * 128;   // over B
    const int tid = threadIdx.x;
    const int tx = tid & 15, ty = tid >> 4;

    float acc[8][8];
#pragma unroll
    for (int i = 0; i < 8; i++)
#pragma unroll
        for (int j = 0; j < 8; j++) acc[i][j] = 0.f;

    for (int k0 = 0; k0 < DDIM; k0 += 16) {
        // load A tile 128x16 (subtract b_dec on the fly)
        {
            int t = tid;
#pragma unroll
            for (int r = 0; r < 2; r++, t += 256) {
                int m = t >> 2, q = (t & 3) * 4;
                float4 v  = *(const float4*)(X + (size_t)(bm + m) * DDIM + k0 + q);
                float4 bd = *(const float4*)(b_dec + k0 + q);
                As[q + 0][m] = v.x - bd.x;
                As[q + 1][m] = v.y - bd.y;
                As[q + 2][m] = v.z - bd.z;
                As[q + 3][m] = v.w - bd.w;
            }
            t = tid;
#pragma unroll
            for (int r = 0; r < 2; r++, t += 256) {
                int n = t >> 2, q = (t & 3) * 4;
                float4 v = *(const float4*)(W + (size_t)(bn + n) * DDIM + k0 + q);
                Ws[q + 0][n] = v.x;
                Ws[q + 1][n] = v.y;
                Ws[q + 2][n] = v.z;
                Ws[q + 3][n] = v.w;
            }
        }
        __syncthreads();
#pragma unroll
        for (int k = 0; k < 16; k++) {
            float a[8], w[8];
            *(float4*)&a[0] = *(const float4*)&As[k][ty * 8];
            *(float4*)&a[4] = *(const float4*)&As[k][ty * 8 + 4];
            *(float4*)&w[0] = *(const float4*)&Ws[k][tx * 8];
            *(float4*)&w[4] = *(const float4*)&Ws[k][tx * 8 + 4];
#pragma unroll
            for (int i = 0; i < 8; i++)
#pragma unroll
                for (int j = 0; j < 8; j++)
                    acc[i][j] += a[i] * w[j];
        }
        __syncthreads();
    }

    float be[8];
#pragma unroll
    for (int j = 0; j < 8; j++) be[j] = b_enc[bn + tx * 8 + j];
#pragma unroll
    for (int i = 0; i < 8; i++) {
        size_t row = (size_t)(bm + ty * 8 + i) * FDIM + bn + tx * 8;
        float4 o0, o1;
        o0.x = fmaxf(acc[i][0] + be[0], 0.f);
        o0.y = fmaxf(acc[i][1] + be[1], 0.f);
        o0.z = fmaxf(acc[i][2] + be[2], 0.f);
        o0.w = fmaxf(acc[i][3] + be[3], 0.f);
        o1.x = fmaxf(acc[i][4] + be[4], 0.f);
        o1.y = fmaxf(acc[i][5] + be[5], 0.f);
        o1.z = fmaxf(acc[i][6] + be[6], 0.f);
        o1.w = fmaxf(acc[i][7] + be[7], 0.f);
        *(float4*)(g_pre + row)     = o0;
        *(float4*)(g_pre + row + 4) = o1;
    }
}

// ---------------- top-64 per row (tournament: per-thread max + rescans) ----------------
// 256 threads; thread t owns indices {t + 256*j : j in [0,96)}
__global__ void topk_kernel(int which)
{
    const int b = blockIdx.x;
    const float* row = g_pre + (size_t)b * FDIM;
    const int t = threadIdx.x;
    __shared__ float s_val[256];
    __shared__ int   s_idx[256];
    __shared__ int   s_wi;

    unsigned long long mask0 = 0ull, mask1 = 0ull;  // 96 ownership bits

    float mv = -1.f;
    int mi = t;
    for (int j = 0; j < 96; j++) {
        float v = row[t + j * 256];
        if (v > mv) { mv = v; mi = t + j * 256; }   // strict > keeps lowest index on ties
    }
    s_val[t] = mv; s_idx[t] = mi;
    __syncthreads();

    for (int k = 0; k < KTOP; k++) {
        if (t < 32) {
            float v = s_val[t];
            int   i = s_idx[t];
#pragma unroll
            for (int o = 1; o < 8; o++) {
                float v2 = s_val[t + o * 32];
                int   i2 = s_idx[t + o * 32];
                if (v2 > v || (v2 == v && i2 < i)) { v = v2; i = i2; }
            }
#pragma unroll
            for (int o = 16; o > 0; o >>= 1) {
                float v2 = __shfl_down_sync(0xffffffffu, v, o);
                int   i2 = __shfl_down_sync(0xffffffffu, i, o);
                if (v2 > v || (v2 == v && i2 < i)) { v = v2; i = i2; }
            }
            if (t == 0) {
                s_wi = i;
                if (which == 0) { g_upvals[b * KTOP + k] = v;  g_upidx[b * KTOP + k] = i; }
                else            { g_downvals[b * KTOP + k] = v; g_downidx[b * KTOP + k] = i; }
            }
        }
        __syncthreads();
        int wi = s_wi;
        if ((wi & 255) == t) {
            int j = wi >> 8;
            if (j < 64) mask0 |= 1ull << j; else mask1 |= 1ull << (j - 64);
            float nv = -1.f;
            int ni = t;
            for (int jj = 0; jj < 96; jj++) {
                bool masked = (jj < 64) ? ((mask0 >> jj) & 1ull) : ((mask1 >> (jj - 64)) & 1ull);
                if (masked) continue;
                float v = row[t + jj * 256];
                if (v > nv) { nv = v; ni = t + jj * 256; }
            }
            s_val[t] = nv; s_idx[t] = ni;
        }
        __syncthreads();
    }
}

// ---------------- contributions: approx_acts[b,kd] ----------------
// one warp per (b, kd); ballot-match against connections row, lazy dot products
// NOTE: connections arrives as int32 (JAX x64 disabled demotes jnp.int64 -> int32)
__global__ void contrib_kernel(const int* __restrict__ conn,
                               const float* __restrict__ W_enc_down)
{
    const int b = blockIdx.x;
    const int w = threadIdx.x >> 5, lane = threadIdx.x & 31;
    __shared__ int   s_ui[KTOP];
    __shared__ float s_uv[KTOP];
    if (threadIdx.x < KTOP) {
        s_ui[threadIdx.x] = g_upidx[b * KTOP + threadIdx.x];
        s_uv[threadIdx.x] = g_upvals[b * KTOP + threadIdx.x];
    }
    __syncthreads();

    for (int kd = w; kd < KTOP; kd += 8) {
        int fd = g_downidx[b * KTOP + kd];
        int ci = conn[(size_t)fd * CONN + lane];   // -1 padded, never matches fu >= 0

        float partial = 0.f;
        bool loaded = false;
        float er[24];
        for (int ku = 0; ku < KTOP; ku++) {
            int fu = s_ui[ku];
            unsigned m = __ballot_sync(0xffffffffu, ci == fu);
            if (m) {
                if (!loaded) {
#pragma unroll
                    for (int i = 0; i < 24; i++)
                        er[i] = W_enc_down[(size_t)fd * DDIM + lane + i * 32];
                    loaded = true;
                }
                float cnt = (float)__popc(m);
                const float* up = g_WupT + (size_t)fu * DDIM + lane;
                float dot = 0.f;
#pragma unroll
                for (int i = 0; i < 24; i++) dot += er[i] * up[i * 32];
                partial += dot * cnt * s_uv[ku];
            }
        }
#pragma unroll
        for (int o = 16; o > 0; o >>= 1)
            partial += __shfl_down_sync(0xffffffffu, partial, o);
        if (lane == 0) g_approx[b * KTOP + kd] = partial;
    }
}

// ---------------- sparse decode: out[b,:] = b_dec + sum_k vals[k] * WdecT[idx[k], :] ----------------
__global__ void recon_kernel(int which, const float* __restrict__ b_dec, float* __restrict__ out)
{
    const int b = blockIdx.x;
    const int t = threadIdx.x;  // 256
    __shared__ float sv[KTOP];
    __shared__ int   si[KTOP];
    if (t < KTOP) {
        if (which == 0) { sv[t] = g_upvals[b * KTOP + t]; si[t] = g_upidx[b * KTOP + t]; }
        else            { sv[t] = g_approx[b * KTOP + t]; si[t] = g_downidx[b * KTOP + t]; }
    }
    __syncthreads();
    const float* WT = (which == 0) ? g_WupT : g_WdownT;

    float a0 = b_dec[t], a1 = b_dec[t + 256], a2 = b_dec[t + 512];
    for (int k = 0; k < KTOP; k++) {
        const float* p = WT + (size_t)si[k] * DDIM + t;
        float v = sv[k];
        a0 += v * p[0];
        a1 += v * p[256];
        a2 += v * p[512];
    }
    size_t o = (size_t)b * DDIM + t;
    out[o]       = a0;
    out[o + 256] = a1;
    out[o + 512] = a2;
}

// ---------------- launch ----------------
extern "C" void kernel_launch(void* const* d_in, const int* in_sizes, int n_in,
                              void* d_out, int out_size)
{
    (void)in_sizes; (void)n_in; (void)out_size;
    const float* x_up       = (const float*)d_in[0];
    const float* x_down     = (const float*)d_in[1];
    const float* W_enc_up   = (const float*)d_in[2];
    const float* b_enc_up   = (const float*)d_in[3];
    const float* W_dec_up   = (const float*)d_in[4];
    const float* b_dec_up   = (const float*)d_in[5];
    const float* W_enc_down = (const float*)d_in[6];
    const float* b_enc_down = (const float*)d_in[7];
    const float* W_dec_down = (const float*)d_in[8];
    const float* b_dec_down = (const float*)d_in[9];
    const int*   connections = (const int*)d_in[10];
    float* out = (float*)d_out;

    dim3 tb(32, 8);
    transpose_kernel<<<dim3(FDIM / 32, DDIM / 32), tb>>>(W_dec_up, 0);
    transpose_kernel<<<dim3(FDIM / 32, DDIM / 32), tb>>>(W_dec_down, 1);

    dim3 gemm_grid(FDIM / 128, B_TOK / 128);
    encode_gemm_kernel<<<gemm_grid, 256>>>(x_up, W_enc_up, b_enc_up, b_dec_up);
    topk_kernel<<<B_TOK, 256>>>(0);
    recon_kernel<<<B_TOK, 256>>>(0, b_dec_up, out);

    encode_gemm_kernel<<<gemm_grid, 256>>>(x_down, W_enc_down, b_enc_down, b_dec_down);
    topk_kernel<<<B_TOK, 256>>>(1);
    contrib_kernel<<<B_TOK, 256>>>(connections, W_enc_down);
    recon_kernel<<<B_TOK, 256>>>(1, b_dec_down, out + (size_t)B_TOK * DDIM);
}

// round 7
// speedup vs baseline: 1.2432x; 1.2432x over previous
#include <cuda_runtime.h>

#define B_TOK 1024
#define DDIM  768
#define FDIM  24576
#define KTOP  64
#define CONN  32

// ---------------- scratch (device globals: no allocation allowed) ----------------
__device__ float g_pre[(size_t)B_TOK * FDIM];        // reused for up then down
__device__ float g_WupT[(size_t)FDIM * DDIM];        // W_dec_up^T   [F, D]
__device__ float g_WdownT[(size_t)FDIM * DDIM];      // W_dec_down^T [F, D]
__device__ float g_upvals[B_TOK * KTOP];
__device__ int   g_upidx[B_TOK * KTOP];
__device__ float g_downvals[B_TOK * KTOP];
__device__ int   g_downidx[B_TOK * KTOP];
__device__ float g_approx[B_TOK * KTOP];

// ---------------- transpose W_dec [D, F] -> [F, D] ----------------
__global__ void transpose_kernel(const float* __restrict__ in, int which)
{
    __shared__ float tile[32][33];
    float* out = (which == 0) ? g_WupT : g_WdownT;
    int f0 = blockIdx.x * 32;
    int d0 = blockIdx.y * 32;
    int x = threadIdx.x, y = threadIdx.y;  // 32 x 8
#pragma unroll
    for (int j = 0; j < 32; j += 8)
        tile[y + j][x] = in[(size_t)(d0 + y + j) * FDIM + f0 + x];
    __syncthreads();
#pragma unroll
    for (int j = 0; j < 32; j += 8)
        out[(size_t)(f0 + y + j) * DDIM + d0 + x] = tile[x][y + j];
}

// ---------------- encode GEMM: pre = relu((X - b_dec) @ W^T + b_enc) ----------------
// PROVEN in round 2. X: [B, D] row-major, W: [F, D] row-major, pre: [B, F]
// 128x128 tile, BK=16, 256 threads, 8x8 per thread
__global__ __launch_bounds__(256, 2)
void encode_gemm_kernel(const float* __restrict__ X, const float* __restrict__ W,
                        const float* __restrict__ b_enc, const float* __restrict__ b_dec)
{
    __shared__ float As[16][128];
    __shared__ float Ws[16][128];
    const int bn = blockIdx.x * 128;   // over F
    const int bm = blockIdx.y * 128;   // over B
    const int tid = threadIdx.x;
    const int tx = tid & 15, ty = tid >> 4;

    float acc[8][8];
#pragma unroll
    for (int i = 0; i < 8; i++)
#pragma unroll
        for (int j = 0; j < 8; j++) acc[i][j] = 0.f;

    for (int k0 = 0; k0 < DDIM; k0 += 16) {
        {
            int t = tid;
#pragma unroll
            for (int r = 0; r < 2; r++, t += 256) {
                int m = t >> 2, q = (t & 3) * 4;
                float4 v  = *(const float4*)(X + (size_t)(bm + m) * DDIM + k0 + q);
                float4 bd = *(const float4*)(b_dec + k0 + q);
                As[q + 0][m] = v.x - bd.x;
                As[q + 1][m] = v.y - bd.y;
                As[q + 2][m] = v.z - bd.z;
                As[q + 3][m] = v.w - bd.w;
            }
            t = tid;
#pragma unroll
            for (int r = 0; r < 2; r++, t += 256) {
                int n = t >> 2, q = (t & 3) * 4;
                float4 v = *(const float4*)(W + (size_t)(bn + n) * DDIM + k0 + q);
                Ws[q + 0][n] = v.x;
                Ws[q + 1][n] = v.y;
                Ws[q + 2][n] = v.z;
                Ws[q + 3][n] = v.w;
            }
        }
        __syncthreads();
#pragma unroll
        for (int k = 0; k < 16; k++) {
            float a[8], w[8];
            *(float4*)&a[0] = *(const float4*)&As[k][ty * 8];
            *(float4*)&a[4] = *(const float4*)&As[k][ty * 8 + 4];
            *(float4*)&w[0] = *(const float4*)&Ws[k][tx * 8];
            *(float4*)&w[4] = *(const float4*)&Ws[k][tx * 8 + 4];
#pragma unroll
            for (int i = 0; i < 8; i++)
#pragma unroll
                for (int j = 0; j < 8; j++)
                    acc[i][j] += a[i] * w[j];
        }
        __syncthreads();
    }

    float be[8];
#pragma unroll
    for (int j = 0; j < 8; j++) be[j] = b_enc[bn + tx * 8 + j];
#pragma unroll
    for (int i = 0; i < 8; i++) {
        size_t row = (size_t)(bm + ty * 8 + i) * FDIM + bn + tx * 8;
        float4 o0, o1;
        o0.x = fmaxf(acc[i][0] + be[0], 0.f);
        o0.y = fmaxf(acc[i][1] + be[1], 0.f);
        o0.z = fmaxf(acc[i][2] + be[2], 0.f);
        o0.w = fmaxf(acc[i][3] + be[3], 0.f);
        o1.x = fmaxf(acc[i][4] + be[4], 0.f);
        o1.y = fmaxf(acc[i][5] + be[5], 0.f);
        o1.z = fmaxf(acc[i][6] + be[6], 0.f);
        o1.w = fmaxf(acc[i][7] + be[7], 0.f);
        *(float4*)(g_pre + row)     = o0;
        *(float4*)(g_pre + row + 4) = o1;
    }
}

// ---------------- exact top-64 via radix select (the ONE new component) ----------------
// bins = top 11 bits of float bits (positive floats sort monotonically in uint).
// Winners in bins > bstar are all in the top-64; boundary bin resolved exactly
// with value-desc / index-asc tie-break (matches jax.lax.top_k).
__global__ void topk_select_kernel(int which)
{
    const int b = blockIdx.x, t = threadIdx.x;   // 256 threads
    const float* row = g_pre + (size_t)b * FDIM;
    __shared__ int   hist[2048];
    __shared__ int   sc[256];
    __shared__ int   s_bstar, s_nabove, s_ncand;
    __shared__ int   cidx[1024];
    __shared__ float cval[1024];

    for (int i = t; i < 2048; i += 256) hist[i] = 0;
    __syncthreads();
    for (int j = 0; j < 96; j++) {
        float v = row[t + (j << 8)];
        if (v > 0.f) atomicAdd(&hist[__float_as_uint(v) >> 21], 1);
    }
    __syncthreads();
    {
        int s = 0;
#pragma unroll
        for (int i = 0; i < 8; i++) s += hist[t * 8 + i];
        sc[t] = s;
    }
    __syncthreads();
    if (t == 0) {
        int cum = 0, bstar = 0, nab = 0;
        bool found = false;
        for (int s = 255; s >= 0 && !found; s--) {
            int sv = sc[s];
            if (sv == 0) continue;
            if (cum + sv >= KTOP) {
                for (int bi = s * 8 + 7; bi >= s * 8; bi--) {
                    int h = hist[bi];
                    if (cum + h >= KTOP) { bstar = bi; nab = cum; found = true; break; }
                    cum += h;
                }
            } else cum += sv;
        }
        if (!found) { bstar = 0; nab = cum; }
        s_bstar = bstar; s_nabove = nab;
    }
    __syncthreads();
    const unsigned bstar = (unsigned)s_bstar;
    const int nabove = s_nabove;

    float* ov = ((which == 0) ? g_upvals : g_downvals) + b * KTOP;
    int*   oi = ((which == 0) ? g_upidx  : g_downidx)  + b * KTOP;

    // definite winners (bin > bstar), deterministic slots via block scan
    int cnt = 0;
    for (int j = 0; j < 96; j++) {
        float v = row[t + (j << 8)];
        if (v > 0.f && (__float_as_uint(v) >> 21) > bstar) cnt++;
    }
    sc[t] = cnt; __syncthreads();
    for (int o = 1; o < 256; o <<= 1) {
        int vv = (t >= o) ? sc[t - o] : 0;
        __syncthreads(); sc[t] += vv; __syncthreads();
    }
    {
        int pos = sc[t] - cnt, left = cnt;
        for (int j = 0; j < 96 && left > 0; j++) {
            int idx = t + (j << 8);
            float v = row[idx];
            if (v > 0.f && (__float_as_uint(v) >> 21) > bstar) {
                ov[pos] = v; oi[pos] = idx; pos++; left--;
            }
        }
    }
    __syncthreads();

    // boundary-bin candidates
    int ccnt = 0;
    for (int j = 0; j < 96; j++) {
        float v = row[t + (j << 8)];
        if (v > 0.f && (__float_as_uint(v) >> 21) == bstar) ccnt++;
    }
    sc[t] = ccnt; __syncthreads();
    for (int o = 1; o < 256; o <<= 1) {
        int vv = (t >= o) ? sc[t - o] : 0;
        __syncthreads(); sc[t] += vv; __syncthreads();
    }
    if (t == 255) s_ncand = (sc[255] < 1024) ? sc[255] : 1024;
    {
        int cpos = sc[t] - ccnt, left = ccnt;
        for (int j = 0; j < 96 && left > 0; j++) {
            int idx = t + (j << 8);
            float v = row[idx];
            if (v > 0.f && (__float_as_uint(v) >> 21) == bstar) {
                if (cpos < 1024) { cidx[cpos] = idx; cval[cpos] = v; }
                cpos++; left--;
            }
        }
    }
    __syncthreads();

    // exact remaining selection (value desc, index asc) by warp 0
    if (t < 32) {
        const int need = KTOP - nabove;
        const int ncand = s_ncand;
        for (int r2 = 0; r2 < need; r2++) {
            float bv = -1.f; int bidx = 0x7fffffff; int bslot = -1;
            for (int i = t; i < ncand; i += 32) {
                int ix = cidx[i];
                if (ix >= 0) {
                    float v = cval[i];
                    if (v > bv || (v == bv && ix < bidx)) { bv = v; bidx = ix; bslot = i; }
                }
            }
#pragma unroll
            for (int o = 16; o > 0; o >>= 1) {
                float v2 = __shfl_down_sync(0xffffffffu, bv, o);
                int   i2 = __shfl_down_sync(0xffffffffu, bidx, o);
                int   s2 = __shfl_down_sync(0xffffffffu, bslot, o);
                if (v2 > bv || (v2 == bv && i2 < bidx)) { bv = v2; bidx = i2; bslot = s2; }
            }
            bv = __shfl_sync(0xffffffffu, bv, 0);
            bidx = __shfl_sync(0xffffffffu, bidx, 0);
            bslot = __shfl_sync(0xffffffffu, bslot, 0);
            if (t == 0 && bslot >= 0) {
                ov[nabove + r2] = bv; oi[nabove + r2] = bidx; cidx[bslot] = -1;
            }
            __syncwarp();
        }
    }
}

// ---------------- contributions: approx_acts[b,kd] (PROVEN round 2) ----------------
__global__ void contrib_kernel(const int* __restrict__ conn,
                               const float* __restrict__ W_enc_down)
{
    const int b = blockIdx.x;
    const int w = threadIdx.x >> 5, lane = threadIdx.x & 31;
    __shared__ int   s_ui[KTOP];
    __shared__ float s_uv[KTOP];
    if (threadIdx.x < KTOP) {
        s_ui[threadIdx.x] = g_upidx[b * KTOP + threadIdx.x];
        s_uv[threadIdx.x] = g_upvals[b * KTOP + threadIdx.x];
    }
    __syncthreads();

    for (int kd = w; kd < KTOP; kd += 8) {
        int fd = g_downidx[b * KTOP + kd];
        int ci = conn[(size_t)fd * CONN + lane];

        float partial = 0.f;
        bool loaded = false;
        float er[24];
        for (int ku = 0; ku < KTOP; ku++) {
            int fu = s_ui[ku];
            unsigned m = __ballot_sync(0xffffffffu, ci == fu);
            if (m) {
                if (!loaded) {
#pragma unroll
                    for (int i = 0; i < 24; i++)
                        er[i] = W_enc_down[(size_t)fd * DDIM + lane + i * 32];
                    loaded = true;
                }
                float cntf = (float)__popc(m);
                const float* up = g_WupT + (size_t)fu * DDIM + lane;
                float dot = 0.f;
#pragma unroll
                for (int i = 0; i < 24; i++) dot += er[i] * up[i * 32];
                partial += dot * cntf * s_uv[ku];
            }
        }
#pragma unroll
        for (int o = 16; o > 0; o >>= 1)
            partial += __shfl_down_sync(0xffffffffu, partial, o);
        if (lane == 0) g_approx[b * KTOP + kd] = partial;
    }
}

// ---------------- sparse decode (PROVEN round 2) ----------------
__global__ void recon_kernel(int which, const float* __restrict__ b_dec, float* __restrict__ out)
{
    const int b = blockIdx.x;
    const int t = threadIdx.x;  // 256
    __shared__ float sv[KTOP];
    __shared__ int   si[KTOP];
    if (t < KTOP) {
        if (which == 0) { sv[t] = g_upvals[b * KTOP + t]; si[t] = g_upidx[b * KTOP + t]; }
        else            { sv[t] = g_approx[b * KTOP + t]; si[t] = g_downidx[b * KTOP + t]; }
    }
    __syncthreads();
    const float* WT = (which == 0) ? g_WupT : g_WdownT;

    float a0 = b_dec[t], a1 = b_dec[t + 256], a2 = b_dec[t + 512];
    for (int k = 0; k < KTOP; k++) {
        const float* p = WT + (size_t)si[k] * DDIM + t;
        float v = sv[k];
        a0 += v * p[0];
        a1 += v * p[256];
        a2 += v * p[512];
    }
    size_t o = (size_t)b * DDIM + t;
    out[o]       = a0;
    out[o + 256] = a1;
    out[o + 512] = a2;
}

// ---------------- launch ----------------
extern "C" void kernel_launch(void* const* d_in, const int* in_sizes, int n_in,
                              void* d_out, int out_size)
{
    (void)in_sizes; (void)n_in; (void)out_size;
    const float* x_up       = (const float*)d_in[0];
    const float* x_down     = (const float*)d_in[1];
    const float* W_enc_up   = (const float*)d_in[2];
    const float* b_enc_up   = (const float*)d_in[3];
    const float* W_dec_up   = (const float*)d_in[4];
    const float* b_dec_up   = (const float*)d_in[5];
    const float* W_enc_down = (const float*)d_in[6];
    const float* b_enc_down = (const float*)d_in[7];
    const float* W_dec_down = (const float*)d_in[8];
    const float* b_dec_down = (const float*)d_in[9];
    const int*   connections = (const int*)d_in[10];
    float* out = (float*)d_out;

    dim3 tb(32, 8);
    transpose_kernel<<<dim3(FDIM / 32, DDIM / 32), tb>>>(W_dec_up, 0);
    transpose_kernel<<<dim3(FDIM / 32, DDIM / 32), tb>>>(W_dec_down, 1);

    dim3 gemm_grid(FDIM / 128, B_TOK / 128);
    encode_gemm_kernel<<<gemm_grid, 256>>>(x_up, W_enc_up, b_enc_up, b_dec_up);
    topk_select_kernel<<<B_TOK, 256>>>(0);
    recon_kernel<<<B_TOK, 256>>>(0, b_dec_up, out);

    encode_gemm_kernel<<<gemm_grid, 256>>>(x_down, W_enc_down, b_enc_down, b_dec_down);
    topk_select_kernel<<<B_TOK, 256>>>(1);
    contrib_kernel<<<B_TOK, 256>>>(connections, W_enc_down);
    recon_kernel<<<B_TOK, 256>>>(1, b_dec_down, out + (size_t)B_TOK * DDIM);
}

// round 9
// speedup vs baseline: 2.1790x; 1.7527x over previous
#include <cuda_runtime.h>
#include <cuda_fp16.h>
#include <mma.h>
#include <cstdint>

using namespace nvcuda;

#define B_TOK 1024
#define DDIM  768
#define FDIM  24576
#define KTOP  64
#define CONN  32

// ---------------- scratch (device globals: no allocation allowed) ----------------
__device__ float g_pre[(size_t)B_TOK * FDIM];
__device__ float g_WupT[(size_t)FDIM * DDIM];        // W_dec_up^T   [F, D]
__device__ float g_WdownT[(size_t)FDIM * DDIM];      // W_dec_down^T [F, D]
__device__ float g_upvals[B_TOK * KTOP];
__device__ int   g_upidx[B_TOK * KTOP];
__device__ float g_downvals[B_TOK * KTOP];
__device__ int   g_downidx[B_TOK * KTOP];
__device__ float g_approx[B_TOK * KTOP];

// ---------------- transpose W_dec [D, F] -> [F, D] (PROVEN) ----------------
__global__ void transpose_kernel(const float* __restrict__ in, int which)
{
    __shared__ float tile[32][33];
    float* out = (which == 0) ? g_WupT : g_WdownT;
    int f0 = blockIdx.x * 32;
    int d0 = blockIdx.y * 32;
    int x = threadIdx.x, y = threadIdx.y;  // 32 x 8
#pragma unroll
    for (int j = 0; j < 32; j += 8)
        tile[y + j][x] = in[(size_t)(d0 + y + j) * FDIM + f0 + x];
    __syncthreads();
#pragma unroll
    for (int j = 0; j < 32; j += 8)
        out[(size_t)(f0 + y + j) * DDIM + d0 + x] = tile[x][y + j];
}

// ---------------- WMMA encode GEMM: pre = relu((X-b_dec)@W^T + b_enc) ----------------
// fp16 2-way split in-kernel: (x*64) = hi + mid; 3 products hh+hm+mh, fp32 acc, /4096.
// Block tile 128(B) x 128(F), BK=16, 8 warps as 2(m) x 4(n), warp tile 64x32.
#define TP 136    // half pitch per k-row (272 B, 16B-multiple)
#define SP 24     // staging pitch in floats (96 B)

__global__ __launch_bounds__(256, 2)
void gemm_wmma_kernel(const float* __restrict__ X, const float* __restrict__ W,
                      const float* __restrict__ b_enc, const float* __restrict__ b_dec)
{
    __shared__ __align__(32) __half Ah[16][TP];
    __shared__ __align__(32) __half Am[16][TP];
    __shared__ __align__(32) __half Wh[16][TP];
    __shared__ __align__(32) __half Wm[16][TP];
    __shared__ __align__(32) float  stage[8][16 * SP];

    const int tid = threadIdx.x;
    const int wid = tid >> 5, lane = tid & 31;
    const int wm = wid >> 2, wn = wid & 3;     // warp tile: rows [wm*64,+64), cols [wn*32,+32)
    const int bm = blockIdx.x * 128;           // over B
    const int bn = blockIdx.y * 128;           // over F

    wmma::fragment<wmma::accumulator, 16, 16, 16, float> c[4][2];
#pragma unroll
    for (int mf = 0; mf < 4; mf++)
#pragma unroll
        for (int nf = 0; nf < 2; nf++)
            wmma::fill_fragment(c[mf][nf], 0.f);

    for (int k0 = 0; k0 < DDIM; k0 += 16) {
        // ---- load + convert A tile (PROVEN R2 mapping) ----
        {
            int t = tid;
#pragma unroll
            for (int r = 0; r < 2; r++, t += 256) {
                int m = t >> 2, q = (t & 3) * 4;
                float4 v  = *(const float4*)(X + (size_t)(bm + m) * DDIM + k0 + q);
                float4 bd = *(const float4*)(b_dec + k0 + q);
                float f[4] = {v.x - bd.x, v.y - bd.y, v.z - bd.z, v.w - bd.w};
#pragma unroll
                for (int j = 0; j < 4; j++) {
                    float fs = f[j] * 64.f;
                    __half h = __float2half_rn(fs);
                    Ah[q + j][m] = h;
                    Am[q + j][m] = __float2half_rn(fs - __half2float(h));
                }
            }
            t = tid;
#pragma unroll
            for (int r = 0; r < 2; r++, t += 256) {
                int n = t >> 2, q = (t & 3) * 4;
                float4 v = *(const float4*)(W + (size_t)(bn + n) * DDIM + k0 + q);
                float f[4] = {v.x, v.y, v.z, v.w};
#pragma unroll
                for (int j = 0; j < 4; j++) {
                    float fs = f[j] * 64.f;
                    __half h = __float2half_rn(fs);
                    Wh[q + j][n] = h;
                    Wm[q + j][n] = __float2half_rn(fs - __half2float(h));
                }
            }
        }
        __syncthreads();

        // ---- compute: 3-product split via wmma ----
        wmma::fragment<wmma::matrix_a, 16, 16, 16, __half, wmma::col_major> ah[4], am[4];
#pragma unroll
        for (int mf = 0; mf < 4; mf++) {
            wmma::load_matrix_sync(ah[mf], &Ah[0][wm * 64 + mf * 16], TP);
            wmma::load_matrix_sync(am[mf], &Am[0][wm * 64 + mf * 16], TP);
        }
#pragma unroll
        for (int nf = 0; nf < 2; nf++) {
            wmma::fragment<wmma::matrix_b, 16, 16, 16, __half, wmma::row_major> bh, bm2;
            wmma::load_matrix_sync(bh,  &Wh[0][wn * 32 + nf * 16], TP);
            wmma::load_matrix_sync(bm2, &Wm[0][wn * 32 + nf * 16], TP);
#pragma unroll
            for (int mf = 0; mf < 4; mf++) {
                wmma::mma_sync(c[mf][nf], ah[mf], bh,  c[mf][nf]);
                wmma::mma_sync(c[mf][nf], ah[mf], bm2, c[mf][nf]);
                wmma::mma_sync(c[mf][nf], am[mf], bh,  c[mf][nf]);
            }
        }
        __syncthreads();
    }

    // ---- epilogue: stage each 16x16 frag, unscale + bias + relu, write global ----
    const float inv = 1.f / 4096.f;
    const int r2 = lane >> 1, cq = (lane & 1) * 8;
#pragma unroll
    for (int mf = 0; mf < 4; mf++) {
#pragma unroll
        for (int nf = 0; nf < 2; nf++) {
            wmma::store_matrix_sync(&stage[wid][0], c[mf][nf], SP, wmma::mem_row_major);
            __syncwarp();
            int grow = bm + wm * 64 + mf * 16 + r2;
            int gcol = bn + wn * 32 + nf * 16 + cq;
            float4 s0 = *(const float4*)(&stage[wid][r2 * SP + cq]);
            float4 s1 = *(const float4*)(&stage[wid][r2 * SP + cq + 4]);
            float4 o0, o1;
            o0.x = fmaxf(s0.x * inv + b_enc[gcol + 0], 0.f);
            o0.y = fmaxf(s0.y * inv + b_enc[gcol + 1], 0.f);
            o0.z = fmaxf(s0.z * inv + b_enc[gcol + 2], 0.f);
            o0.w = fmaxf(s0.w * inv + b_enc[gcol + 3], 0.f);
            o1.x = fmaxf(s1.x * inv + b_enc[gcol + 4], 0.f);
            o1.y = fmaxf(s1.y * inv + b_enc[gcol + 5], 0.f);
            o1.z = fmaxf(s1.z * inv + b_enc[gcol + 6], 0.f);
            o1.w = fmaxf(s1.w * inv + b_enc[gcol + 7], 0.f);
            *(float4*)(g_pre + (size_t)grow * FDIM + gcol)     = o0;
            *(float4*)(g_pre + (size_t)grow * FDIM + gcol + 4) = o1;
            __syncwarp();
        }
    }
}

// ---------------- exact top-64 via radix select (PROVEN round 7) ----------------
__global__ void topk_select_kernel(int which)
{
    const int b = blockIdx.x, t = threadIdx.x;   // 256 threads
    const float* row = g_pre + (size_t)b * FDIM;
    __shared__ int   hist[2048];
    __shared__ int   sc[256];
    __shared__ int   s_bstar, s_nabove, s_ncand;
    __shared__ int   cidx[1024];
    __shared__ float cval[1024];

    for (int i = t; i < 2048; i += 256) hist[i] = 0;
    __syncthreads();
    for (int j = 0; j < 96; j++) {
        float v = row[t + (j << 8)];
        if (v > 0.f) atomicAdd(&hist[__float_as_uint(v) >> 21], 1);
    }
    __syncthreads();
    {
        int s = 0;
#pragma unroll
        for (int i = 0; i < 8; i++) s += hist[t * 8 + i];
        sc[t] = s;
    }
    __syncthreads();
    if (t == 0) {
        int cum = 0, bstar = 0, nab = 0;
        bool found = false;
        for (int s = 255; s >= 0 && !found; s--) {
            int sv = sc[s];
            if (sv == 0) continue;
            if (cum + sv >= KTOP) {
                for (int bi = s * 8 + 7; bi >= s * 8; bi--) {
                    int h = hist[bi];
                    if (cum + h >= KTOP) { bstar = bi; nab = cum; found = true; break; }
                    cum += h;
                }
            } else cum += sv;
        }
        if (!found) { bstar = 0; nab = cum; }
        s_bstar = bstar; s_nabove = nab;
    }
    __syncthreads();
    const unsigned bstar = (unsigned)s_bstar;
    const int nabove = s_nabove;

    float* ov = ((which == 0) ? g_upvals : g_downvals) + b * KTOP;
    int*   oi = ((which == 0) ? g_upidx  : g_downidx)  + b * KTOP;

    int cnt = 0;
    for (int j = 0; j < 96; j++) {
        float v = row[t + (j << 8)];
        if (v > 0.f && (__float_as_uint(v) >> 21) > bstar) cnt++;
    }
    sc[t] = cnt; __syncthreads();
    for (int o = 1; o < 256; o <<= 1) {
        int vv = (t >= o) ? sc[t - o] : 0;
        __syncthreads(); sc[t] += vv; __syncthreads();
    }
    {
        int pos = sc[t] - cnt, left = cnt;
        for (int j = 0; j < 96 && left > 0; j++) {
            int idx = t + (j << 8);
            float v = row[idx];
            if (v > 0.f && (__float_as_uint(v) >> 21) > bstar) {
                ov[pos] = v; oi[pos] = idx; pos++; left--;
            }
        }
    }
    __syncthreads();

    int ccnt = 0;
    for (int j = 0; j < 96; j++) {
        float v = row[t + (j << 8)];
        if (v > 0.f && (__float_as_uint(v) >> 21) == bstar) ccnt++;
    }
    sc[t] = ccnt; __syncthreads();
    for (int o = 1; o < 256; o <<= 1) {
        int vv = (t >= o) ? sc[t - o] : 0;
        __syncthreads(); sc[t] += vv; __syncthreads();
    }
    if (t == 255) s_ncand = (sc[255] < 1024) ? sc[255] : 1024;
    {
        int cpos = sc[t] - ccnt, left = ccnt;
        for (int j = 0; j < 96 && left > 0; j++) {
            int idx = t + (j << 8);
            float v = row[idx];
            if (v > 0.f && (__float_as_uint(v) >> 21) == bstar) {
                if (cpos < 1024) { cidx[cpos] = idx; cval[cpos] = v; }
                cpos++; left--;
            }
        }
    }
    __syncthreads();

    if (t < 32) {
        const int need = KTOP - nabove;
        const int ncand = s_ncand;
        for (int r = 0; r < need; r++) {
            float bv = -1.f; int bidx = 0x7fffffff; int bslot = -1;
            for (int i = t; i < ncand; i += 32) {
                int ix = cidx[i];
                if (ix >= 0) {
                    float v = cval[i];
                    if (v > bv || (v == bv && ix < bidx)) { bv = v; bidx = ix; bslot = i; }
                }
            }
#pragma unroll
            for (int o = 16; o > 0; o >>= 1) {
                float v2 = __shfl_down_sync(0xffffffffu, bv, o);
                int   i2 = __shfl_down_sync(0xffffffffu, bidx, o);
                int   s2 = __shfl_down_sync(0xffffffffu, bslot, o);
                if (v2 > bv || (v2 == bv && i2 < bidx)) { bv = v2; bidx = i2; bslot = s2; }
            }
            bv = __shfl_sync(0xffffffffu, bv, 0);
            bidx = __shfl_sync(0xffffffffu, bidx, 0);
            bslot = __shfl_sync(0xffffffffu, bslot, 0);
            if (t == 0 && bslot >= 0) {
                ov[nabove + r] = bv; oi[nabove + r] = bidx; cidx[bslot] = -1;
            }
            __syncwarp();
        }
    }
}

// ---------------- contributions: approx_acts[b,kd] (PROVEN) ----------------
__global__ void contrib_kernel(const int* __restrict__ conn,
                               const float* __restrict__ W_enc_down)
{
    const int b = blockIdx.x;
    const int w = threadIdx.x >> 5, lane = threadIdx.x & 31;
    __shared__ int   s_ui[KTOP];
    __shared__ float s_uv[KTOP];
    if (threadIdx.x < KTOP) {
        s_ui[threadIdx.x] = g_upidx[b * KTOP + threadIdx.x];
        s_uv[threadIdx.x] = g_upvals[b * KTOP + threadIdx.x];
    }
    __syncthreads();

    for (int kd = w; kd < KTOP; kd += 8) {
        int fd = g_downidx[b * KTOP + kd];
        int ci = conn[(size_t)fd * CONN + lane];

        float partial = 0.f;
        bool loaded = false;
        float er[24];
        for (int ku = 0; ku < KTOP; ku++) {
            int fu = s_ui[ku];
            unsigned m = __ballot_sync(0xffffffffu, ci == fu);
            if (m) {
                if (!loaded) {
#pragma unroll
                    for (int i = 0; i < 24; i++)
                        er[i] = W_enc_down[(size_t)fd * DDIM + lane + i * 32];
                    loaded = true;
                }
                float cntf = (float)__popc(m);
                const float* up = g_WupT + (size_t)fu * DDIM + lane;
                float dot = 0.f;
#pragma unroll
                for (int i = 0; i < 24; i++) dot += er[i] * up[i * 32];
                partial += dot * cntf * s_uv[ku];
            }
        }
#pragma unroll
        for (int o = 16; o > 0; o >>= 1)
            partial += __shfl_down_sync(0xffffffffu, partial, o);
        if (lane == 0) g_approx[b * KTOP + kd] = partial;
    }
}

// ---------------- sparse decode (PROVEN) ----------------
__global__ void recon_kernel(int which, const float* __restrict__ b_dec, float* __restrict__ out)
{
    const int b = blockIdx.x;
    const int t = threadIdx.x;  // 256
    __shared__ float sv[KTOP];
    __shared__ int   si[KTOP];
    if (t < KTOP) {
        if (which == 0) { sv[t] = g_upvals[b * KTOP + t]; si[t] = g_upidx[b * KTOP + t]; }
        else            { sv[t] = g_approx[b * KTOP + t]; si[t] = g_downidx[b * KTOP + t]; }
    }
    __syncthreads();
    const float* WT = (which == 0) ? g_WupT : g_WdownT;

    float a0 = b_dec[t], a1 = b_dec[t + 256], a2 = b_dec[t + 512];
    for (int k = 0; k < KTOP; k++) {
        const float* p = WT + (size_t)si[k] * DDIM + t;
        float v = sv[k];
        a0 += v * p[0];
        a1 += v * p[256];
        a2 += v * p[512];
    }
    size_t o = (size_t)b * DDIM + t;
    out[o]       = a0;
    out[o + 256] = a1;
    out[o + 512] = a2;
}

// ---------------- launch ----------------
extern "C" void kernel_launch(void* const* d_in, const int* in_sizes, int n_in,
                              void* d_out, int out_size)
{
    (void)in_sizes; (void)n_in; (void)out_size;
    const float* x_up       = (const float*)d_in[0];
    const float* x_down     = (const float*)d_in[1];
    const float* W_enc_up   = (const float*)d_in[2];
    const float* b_enc_up   = (const float*)d_in[3];
    const float* W_dec_up   = (const float*)d_in[4];
    const float* b_dec_up   = (const float*)d_in[5];
    const float* W_enc_down = (const float*)d_in[6];
    const float* b_enc_down = (const float*)d_in[7];
    const float* W_dec_down = (const float*)d_in[8];
    const float* b_dec_down = (const float*)d_in[9];
    const int*   connections = (const int*)d_in[10];
    float* out = (float*)d_out;

    dim3 tb(32, 8);
    dim3 gemm_grid(B_TOK / 128, FDIM / 128);   // x: B tiles (8), y: F tiles (192)

    // ---- upstream ----
    gemm_wmma_kernel<<<gemm_grid, 256>>>(x_up, W_enc_up, b_enc_up, b_dec_up);
    topk_select_kernel<<<B_TOK, 256>>>(0);
    transpose_kernel<<<dim3(FDIM / 32, DDIM / 32), tb>>>(W_dec_up, 0);
    recon_kernel<<<B_TOK, 256>>>(0, b_dec_up, out);

    // ---- downstream ----
    gemm_wmma_kernel<<<gemm_grid, 256>>>(x_down, W_enc_down, b_enc_down, b_dec_down);
    topk_select_kernel<<<B_TOK, 256>>>(1);
    transpose_kernel<<<dim3(FDIM / 32, DDIM / 32), tb>>>(W_dec_down, 1);
    contrib_kernel<<<B_TOK, 256>>>(connections, W_enc_down);
    recon_kernel<<<B_TOK, 256>>>(1, b_dec_down, out + (size_t)B_TOK * DDIM);
}

// round 10
// speedup vs baseline: 2.2355x; 1.0260x over previous
#include <cuda_runtime.h>
#include <cuda_fp16.h>
#include <mma.h>
#include <cstdint>

using namespace nvcuda;

#define B_TOK 1024
#define DDIM  768
#define FDIM  24576
#define KTOP  64
#define CONN  32

// ---------------- scratch (device globals: no allocation allowed) ----------------
__device__ float g_pre[(size_t)B_TOK * FDIM];
__device__ float g_WupT[(size_t)FDIM * DDIM];        // W_dec_up^T   [F, D]
__device__ float g_WdownT[(size_t)FDIM * DDIM];      // W_dec_down^T [F, D]
__device__ float g_upvals[B_TOK * KTOP];
__device__ int   g_upidx[B_TOK * KTOP];
__device__ float g_downvals[B_TOK * KTOP];
__device__ int   g_downidx[B_TOK * KTOP];
__device__ float g_approx[B_TOK * KTOP];

// ---------------- transpose W_dec [D, F] -> [F, D] (PROVEN) ----------------
__global__ void transpose_kernel(const float* __restrict__ in, int which)
{
    __shared__ float tile[32][33];
    float* out = (which == 0) ? g_WupT : g_WdownT;
    int f0 = blockIdx.x * 32;
    int d0 = blockIdx.y * 32;
    int x = threadIdx.x, y = threadIdx.y;  // 32 x 8
#pragma unroll
    for (int j = 0; j < 32; j += 8)
        tile[y + j][x] = in[(size_t)(d0 + y + j) * FDIM + f0 + x];
    __syncthreads();
#pragma unroll
    for (int j = 0; j < 32; j += 8)
        out[(size_t)(f0 + y + j) * DDIM + d0 + x] = tile[x][y + j];
}

// ---------------- WMMA encode GEMM (PROVEN R9) + register-prefetch pipeline ----------------
// pre = relu((X-b_dec)@W^T + b_enc); fp16 split (x64 = hi+mid), hh+hm+mh, fp32 acc, /4096.
#define TP 136    // half pitch per k-row (272 B)
#define SP 24     // staging pitch in floats

__global__ __launch_bounds__(256, 2)
void gemm_wmma_kernel(const float* __restrict__ X, const float* __restrict__ W,
                      const float* __restrict__ b_enc, const float* __restrict__ b_dec)
{
    __shared__ __align__(32) __half Ah[16][TP];
    __shared__ __align__(32) __half Am[16][TP];
    __shared__ __align__(32) __half Wh[16][TP];
    __shared__ __align__(32) __half Wm[16][TP];
    __shared__ __align__(32) float  stage[8][16 * SP];

    const int tid = threadIdx.x;
    const int wid = tid >> 5, lane = tid & 31;
    const int wm = wid >> 2, wn = wid & 3;     // warp tile: rows [wm*64,+64), cols [wn*32,+32)
    const int bm = blockIdx.x * 128;           // over B
    const int bn = blockIdx.y * 128;           // over F

    wmma::fragment<wmma::accumulator, 16, 16, 16, float> c[4][2];
#pragma unroll
    for (int mf = 0; mf < 4; mf++)
#pragma unroll
        for (int nf = 0; nf < 2; nf++)
            wmma::fill_fragment(c[mf][nf], 0.f);

    float4 av[2], wv[2];   // prefetch registers (proven R2 mapping: m = t>>2, q = (t&3)*4)
    auto load_regs = [&](int k0) {
#pragma unroll
        for (int r = 0; r < 2; r++) {
            int t = tid + 256 * r;
            int m = t >> 2, q = (t & 3) * 4;
            av[r] = *(const float4*)(X + (size_t)(bm + m) * DDIM + k0 + q);
            wv[r] = *(const float4*)(W + (size_t)(bn + m) * DDIM + k0 + q);
        }
    };
    auto store_smem = [&](int k0) {
#pragma unroll
        for (int r = 0; r < 2; r++) {
            int t = tid + 256 * r;
            int m = t >> 2, q = (t & 3) * 4;
            float4 bd = *(const float4*)(b_dec + k0 + q);   // L1-resident
            float fa[4] = {av[r].x - bd.x, av[r].y - bd.y, av[r].z - bd.z, av[r].w - bd.w};
            float fw[4] = {wv[r].x, wv[r].y, wv[r].z, wv[r].w};
#pragma unroll
            for (int j = 0; j < 4; j++) {
                float fs = fa[j] * 64.f;
                __half h = __float2half_rn(fs);
                Ah[q + j][m] = h;
                Am[q + j][m] = __float2half_rn(fs - __half2float(h));
                float gs = fw[j] * 64.f;
                __half g = __float2half_rn(gs);
                Wh[q + j][m] = g;
                Wm[q + j][m] = __float2half_rn(gs - __half2float(g));
            }
        }
    };

    load_regs(0);
    for (int k0 = 0; k0 < DDIM; k0 += 16) {
        store_smem(k0);
        __syncthreads();
        if (k0 + 16 < DDIM) load_regs(k0 + 16);   // overlap next loads with compute

        wmma::fragment<wmma::matrix_a, 16, 16, 16, __half, wmma::col_major> ah[4], am[4];
#pragma unroll
        for (int mf = 0; mf < 4; mf++) {
            wmma::load_matrix_sync(ah[mf], &Ah[0][wm * 64 + mf * 16], TP);
            wmma::load_matrix_sync(am[mf], &Am[0][wm * 64 + mf * 16], TP);
        }
#pragma unroll
        for (int nf = 0; nf < 2; nf++) {
            wmma::fragment<wmma::matrix_b, 16, 16, 16, __half, wmma::row_major> bh, bm2;
            wmma::load_matrix_sync(bh,  &Wh[0][wn * 32 + nf * 16], TP);
            wmma::load_matrix_sync(bm2, &Wm[0][wn * 32 + nf * 16], TP);
#pragma unroll
            for (int mf = 0; mf < 4; mf++) {
                wmma::mma_sync(c[mf][nf], ah[mf], bh,  c[mf][nf]);
                wmma::mma_sync(c[mf][nf], ah[mf], bm2, c[mf][nf]);
                wmma::mma_sync(c[mf][nf], am[mf], bh,  c[mf][nf]);
            }
        }
        __syncthreads();
    }

    // ---- epilogue (PROVEN R9) ----
    const float inv = 1.f / 4096.f;
    const int r2 = lane >> 1, cq = (lane & 1) * 8;
#pragma unroll
    for (int mf = 0; mf < 4; mf++) {
#pragma unroll
        for (int nf = 0; nf < 2; nf++) {
            wmma::store_matrix_sync(&stage[wid][0], c[mf][nf], SP, wmma::mem_row_major);
            __syncwarp();
            int grow = bm + wm * 64 + mf * 16 + r2;
            int gcol = bn + wn * 32 + nf * 16 + cq;
            float4 s0 = *(const float4*)(&stage[wid][r2 * SP + cq]);
            float4 s1 = *(const float4*)(&stage[wid][r2 * SP + cq + 4]);
            float4 o0, o1;
            o0.x = fmaxf(s0.x * inv + b_enc[gcol + 0], 0.f);
            o0.y = fmaxf(s0.y * inv + b_enc[gcol + 1], 0.f);
            o0.z = fmaxf(s0.z * inv + b_enc[gcol + 2], 0.f);
            o0.w = fmaxf(s0.w * inv + b_enc[gcol + 3], 0.f);
            o1.x = fmaxf(s1.x * inv + b_enc[gcol + 4], 0.f);
            o1.y = fmaxf(s1.y * inv + b_enc[gcol + 5], 0.f);
            o1.z = fmaxf(s1.z * inv + b_enc[gcol + 6], 0.f);
            o1.w = fmaxf(s1.w * inv + b_enc[gcol + 7], 0.f);
            *(float4*)(g_pre + (size_t)grow * FDIM + gcol)     = o0;
            *(float4*)(g_pre + (size_t)grow * FDIM + gcol + 4) = o1;
            __syncwarp();
        }
    }
}

// ---------------- exact top-64 radix select: 512 threads, 3 fused passes ----------------
__global__ void topk_select_kernel(int which)
{
    const int b = blockIdx.x, t = threadIdx.x;   // 512 threads, 48 elems each
    const float* row = g_pre + (size_t)b * FDIM;
    __shared__ int   hist[2048];
    __shared__ int   sc[512];
    __shared__ int   sc2[512];
    __shared__ int   s_bstar, s_nabove, s_ncand;
    __shared__ int   cidx[1024];
    __shared__ float cval[1024];

    // pass 1: histogram over top-11 bits (positives only)
    for (int i = t; i < 2048; i += 512) hist[i] = 0;
    __syncthreads();
    for (int j = 0; j < 48; j++) {
        float v = row[t + (j << 9)];
        if (v > 0.f) atomicAdd(&hist[__float_as_uint(v) >> 21], 1);
    }
    __syncthreads();
    {
        int s = 0;
#pragma unroll
        for (int i = 0; i < 4; i++) s += hist[t * 4 + i];
        sc[t] = s;
    }
    __syncthreads();
    if (t == 0) {
        int cum = 0, bstar = 0, nab = 0;
        bool found = false;
        for (int s = 511; s >= 0 && !found; s--) {
            int sv = sc[s];
            if (sv == 0) continue;
            if (cum + sv >= KTOP) {
                for (int bi = s * 4 + 3; bi >= s * 4; bi--) {
                    int h = hist[bi];
                    if (cum + h >= KTOP) { bstar = bi; nab = cum; found = true; break; }
                    cum += h;
                }
            } else cum += sv;
        }
        if (!found) { bstar = 0; nab = cum; }
        s_bstar = bstar; s_nabove = nab;
    }
    __syncthreads();
    const unsigned bstar = (unsigned)s_bstar;
    const int nabove = s_nabove;

    float* ov = ((which == 0) ? g_upvals : g_downvals) + b * KTOP;
    int*   oi = ((which == 0) ? g_upidx  : g_downidx)  + b * KTOP;

    // pass 2: fused winner + boundary counts
    int cnt = 0, ccnt = 0;
    for (int j = 0; j < 48; j++) {
        float v = row[t + (j << 9)];
        if (v > 0.f) {
            unsigned bin = __float_as_uint(v) >> 21;
            cnt  += (bin > bstar);
            ccnt += (bin == bstar);
        }
    }
    sc[t] = cnt; sc2[t] = ccnt;
    __syncthreads();
    for (int o = 1; o < 512; o <<= 1) {
        int v1 = (t >= o) ? sc[t - o] : 0;
        int v2 = (t >= o) ? sc2[t - o] : 0;
        __syncthreads();
        sc[t] += v1; sc2[t] += v2;
        __syncthreads();
    }
    if (t == 511) s_ncand = (sc2[511] < 1024) ? sc2[511] : 1024;

    // pass 3: fused writes (deterministic scan-based slots)
    {
        int pos = sc[t] - cnt, cpos = sc2[t] - ccnt;
        int left = cnt + ccnt;
        for (int j = 0; j < 48 && left > 0; j++) {
            int idx = t + (j << 9);
            float v = row[idx];
            if (v > 0.f) {
                unsigned bin = __float_as_uint(v) >> 21;
                if (bin > bstar) {
                    ov[pos] = v; oi[pos] = idx; pos++; left--;
                } else if (bin == bstar) {
                    if (cpos < 1024) { cidx[cpos] = idx; cval[cpos] = v; }
                    cpos++; left--;
                }
            }
        }
    }
    __syncthreads();

    // exact remaining selection (value desc, index asc) by warp 0
    if (t < 32) {
        const int need = KTOP - nabove;
        const int ncand = s_ncand;
        for (int r = 0; r < need; r++) {
            float bv = -1.f; int bidx = 0x7fffffff; int bslot = -1;
            for (int i = t; i < ncand; i += 32) {
                int ix = cidx[i];
                if (ix >= 0) {
                    float v = cval[i];
                    if (v > bv || (v == bv && ix < bidx)) { bv = v; bidx = ix; bslot = i; }
                }
            }
#pragma unroll
            for (int o = 16; o > 0; o >>= 1) {
                float v2 = __shfl_down_sync(0xffffffffu, bv, o);
                int   i2 = __shfl_down_sync(0xffffffffu, bidx, o);
                int   s2 = __shfl_down_sync(0xffffffffu, bslot, o);
                if (v2 > bv || (v2 == bv && i2 < bidx)) { bv = v2; bidx = i2; bslot = s2; }
            }
            bv = __shfl_sync(0xffffffffu, bv, 0);
            bidx = __shfl_sync(0xffffffffu, bidx, 0);
            bslot = __shfl_sync(0xffffffffu, bslot, 0);
            if (t == 0 && bslot >= 0) {
                ov[nabove + r] = bv; oi[nabove + r] = bidx; cidx[bslot] = -1;
            }
            __syncwarp();
        }
    }
}

// ---------------- contributions: approx_acts[b,kd] (PROVEN) ----------------
__global__ void contrib_kernel(const int* __restrict__ conn,
                               const float* __restrict__ W_enc_down)
{
    const int b = blockIdx.x;
    const int w = threadIdx.x >> 5, lane = threadIdx.x & 31;
    __shared__ int   s_ui[KTOP];
    __shared__ float s_uv[KTOP];
    if (threadIdx.x < KTOP) {
        s_ui[threadIdx.x] = g_upidx[b * KTOP + threadIdx.x];
        s_uv[threadIdx.x] = g_upvals[b * KTOP + threadIdx.x];
    }
    __syncthreads();

    for (int kd = w; kd < KTOP; kd += 8) {
        int fd = g_downidx[b * KTOP + kd];
        int ci = conn[(size_t)fd * CONN + lane];

        float partial = 0.f;
        bool loaded = false;
        float er[24];
        for (int ku = 0; ku < KTOP; ku++) {
            int fu = s_ui[ku];
            unsigned m = __ballot_sync(0xffffffffu, ci == fu);
            if (m) {
                if (!loaded) {
#pragma unroll
                    for (int i = 0; i < 24; i++)
                        er[i] = W_enc_down[(size_t)fd * DDIM + lane + i * 32];
                    loaded = true;
                }
                float cntf = (float)__popc(m);
                const float* up = g_WupT + (size_t)fu * DDIM + lane;
                float dot = 0.f;
#pragma unroll
                for (int i = 0; i < 24; i++) dot += er[i] * up[i * 32];
                partial += dot * cntf * s_uv[ku];
            }
        }
#pragma unroll
        for (int o = 16; o > 0; o >>= 1)
            partial += __shfl_down_sync(0xffffffffu, partial, o);
        if (lane == 0) g_approx[b * KTOP + kd] = partial;
    }
}

// ---------------- sparse decode (PROVEN) ----------------
__global__ void recon_kernel(int which, const float* __restrict__ b_dec, float* __restrict__ out)
{
    const int b = blockIdx.x;
    const int t = threadIdx.x;  // 256
    __shared__ float sv[KTOP];
    __shared__ int   si[KTOP];
    if (t < KTOP) {
        if (which == 0) { sv[t] = g_upvals[b * KTOP + t]; si[t] = g_upidx[b * KTOP + t]; }
        else            { sv[t] = g_approx[b * KTOP + t]; si[t] = g_downidx[b * KTOP + t]; }
    }
    __syncthreads();
    const float* WT = (which == 0) ? g_WupT : g_WdownT;

    float a0 = b_dec[t], a1 = b_dec[t + 256], a2 = b_dec[t + 512];
    for (int k = 0; k < KTOP; k++) {
        const float* p = WT + (size_t)si[k] * DDIM + t;
        float v = sv[k];
        a0 += v * p[0];
        a1 += v * p[256];
        a2 += v * p[512];
    }
    size_t o = (size_t)b * DDIM + t;
    out[o]       = a0;
    out[o + 256] = a1;
    out[o + 512] = a2;
}

// ---------------- launch ----------------
extern "C" void kernel_launch(void* const* d_in, const int* in_sizes, int n_in,
                              void* d_out, int out_size)
{
    (void)in_sizes; (void)n_in; (void)out_size;
    const float* x_up       = (const float*)d_in[0];
    const float* x_down     = (const float*)d_in[1];
    const float* W_enc_up   = (const float*)d_in[2];
    const float* b_enc_up   = (const float*)d_in[3];
    const float* W_dec_up   = (const float*)d_in[4];
    const float* b_dec_up   = (const float*)d_in[5];
    const float* W_enc_down = (const float*)d_in[6];
    const float* b_enc_down = (const float*)d_in[7];
    const float* W_dec_down = (const float*)d_in[8];
    const float* b_dec_down = (const float*)d_in[9];
    const int*   connections = (const int*)d_in[10];
    float* out = (float*)d_out;

    dim3 tb(32, 8);
    dim3 gemm_grid(B_TOK / 128, FDIM / 128);   // x: B tiles (8), y: F tiles (192)

    // ---- upstream ----
    gemm_wmma_kernel<<<gemm_grid, 256>>>(x_up, W_enc_up, b_enc_up, b_dec_up);
    topk_select_kernel<<<B_TOK, 512>>>(0);
    transpose_kernel<<<dim3(FDIM / 32, DDIM / 32), tb>>>(W_dec_up, 0);
    recon_kernel<<<B_TOK, 256>>>(0, b_dec_up, out);

    // ---- downstream ----
    gemm_wmma_kernel<<<gemm_grid, 256>>>(x_down, W_enc_down, b_enc_down, b_dec_down);
    topk_select_kernel<<<B_TOK, 512>>>(1);
    transpose_kernel<<<dim3(FDIM / 32, DDIM / 32), tb>>>(W_dec_down, 1);
    contrib_kernel<<<B_TOK, 256>>>(connections, W_enc_down);
    recon_kernel<<<B_TOK, 256>>>(1, b_dec_down, out + (size_t)B_TOK * DDIM);
}

// round 12
// speedup vs baseline: 2.3547x; 1.0533x over previous
#include <cuda_runtime.h>
#include <cuda_fp16.h>
#include <mma.h>
#include <cstdint>

using namespace nvcuda;

#define B_TOK 1024
#define DDIM  768
#define FDIM  24576
#define KTOP  64
#define CONN  32

// ---------------- scratch (device globals: no allocation allowed) ----------------
// NOTE: device globals are ONLY referenced from device code (host-side &global is
// the host shadow symbol — the bug behind rounds 4/5/6/8/11).
__device__ float g_pre[(size_t)B_TOK * FDIM];
__device__ float g_WupT[(size_t)FDIM * DDIM];        // W_dec_up^T   [F, D]
__device__ float g_WdownT[(size_t)FDIM * DDIM];      // W_dec_down^T [F, D]
__device__ __align__(16) __half g_Xh[(size_t)B_TOK * DDIM];
__device__ __align__(16) __half g_Xm[(size_t)B_TOK * DDIM];
__device__ __align__(16) __half g_Wh[(size_t)FDIM * DDIM];
__device__ __align__(16) __half g_Wm[(size_t)FDIM * DDIM];
__device__ float g_upvals[B_TOK * KTOP];
__device__ int   g_upidx[B_TOK * KTOP];
__device__ float g_downvals[B_TOK * KTOP];
__device__ int   g_downidx[B_TOK * KTOP];
__device__ float g_approx[B_TOK * KTOP];

// ---------------- split fp32 -> planar fp16 hi/mid (math identical to PROVEN R9) ----------------
// Writes g_Xh/g_Xm (with b_dec subtracted). Globals referenced IN DEVICE CODE.
__global__ void split_x_kernel(const float* __restrict__ src, const float* __restrict__ b_dec,
                               int n8)
{
    int i = blockIdx.x * blockDim.x + threadIdx.x;
    if (i >= n8) return;
    int col = (i * 8) % DDIM;
    float4 a = ((const float4*)src)[i * 2];
    float4 b = ((const float4*)src)[i * 2 + 1];
    float4 c = *(const float4*)(b_dec + col);
    float4 d = *(const float4*)(b_dec + col + 4);
    float f[8] = {a.x - c.x, a.y - c.y, a.z - c.z, a.w - c.w,
                  b.x - d.x, b.y - d.y, b.z - d.z, b.w - d.w};
    unsigned short hs[8], ms[8];
#pragma unroll
    for (int j = 0; j < 8; j++) {
        float fs = f[j] * 64.f;
        __half h = __float2half_rn(fs);
        hs[j] = __half_as_ushort(h);
        ms[j] = __half_as_ushort(__float2half_rn(fs - __half2float(h)));
    }
    uint4 hv, mv;
    hv.x = hs[0] | ((unsigned)hs[1] << 16); hv.y = hs[2] | ((unsigned)hs[3] << 16);
    hv.z = hs[4] | ((unsigned)hs[5] << 16); hv.w = hs[6] | ((unsigned)hs[7] << 16);
    mv.x = ms[0] | ((unsigned)ms[1] << 16); mv.y = ms[2] | ((unsigned)ms[3] << 16);
    mv.z = ms[4] | ((unsigned)ms[5] << 16); mv.w = ms[6] | ((unsigned)ms[7] << 16);
    ((uint4*)g_Xh)[i] = hv;
    ((uint4*)g_Xm)[i] = mv;
}

__global__ void split_w_kernel(const float* __restrict__ src, int n8)
{
    int i = blockIdx.x * blockDim.x + threadIdx.x;
    if (i >= n8) return;
    float4 a = ((const float4*)src)[i * 2];
    float4 b = ((const float4*)src)[i * 2 + 1];
    float f[8] = {a.x, a.y, a.z, a.w, b.x, b.y, b.z, b.w};
    unsigned short hs[8], ms[8];
#pragma unroll
    for (int j = 0; j < 8; j++) {
        float fs = f[j] * 64.f;
        __half h = __float2half_rn(fs);
        hs[j] = __half_as_ushort(h);
        ms[j] = __half_as_ushort(__float2half_rn(fs - __half2float(h)));
    }
    uint4 hv, mv;
    hv.x = hs[0] | ((unsigned)hs[1] << 16); hv.y = hs[2] | ((unsigned)hs[3] << 16);
    hv.z = hs[4] | ((unsigned)hs[5] << 16); hv.w = hs[6] | ((unsigned)hs[7] << 16);
    mv.x = ms[0] | ((unsigned)ms[1] << 16); mv.y = ms[2] | ((unsigned)ms[3] << 16);
    mv.z = ms[4] | ((unsigned)ms[5] << 16); mv.w = ms[6] | ((unsigned)ms[7] << 16);
    ((uint4*)g_Wh)[i] = hv;
    ((uint4*)g_Wm)[i] = mv;
}

// ---------------- transpose W_dec [D, F] -> [F, D] (PROVEN) ----------------
__global__ void transpose_kernel(const float* __restrict__ in, int which)
{
    __shared__ float tile[32][33];
    float* out = (which == 0) ? g_WupT : g_WdownT;
    int f0 = blockIdx.x * 32;
    int d0 = blockIdx.y * 32;
    int x = threadIdx.x, y = threadIdx.y;  // 32 x 8
#pragma unroll
    for (int j = 0; j < 32; j += 8)
        tile[y + j][x] = in[(size_t)(d0 + y + j) * FDIM + f0 + x];
    __syncthreads();
#pragma unroll
    for (int j = 0; j < 32; j += 8)
        out[(size_t)(f0 + y + j) * DDIM + d0 + x] = tile[x][y + j];
}

// ---------------- WMMA encode GEMM on pre-split fp16 planes ----------------
// pre = relu( (1/4096) * [XhWh + XhWm + XmWh] + b_enc ); A row_major, B col_major,
// SMEM k-contiguous rows (pitch 24 halves; r*12 mod 32 distinct -> conflict-free ldmatrix).
#define TP2 24    // halves per SMEM row (48 B)
#define SP  24    // staging pitch in floats

__global__ __launch_bounds__(256, 2)
void gemm_wmma_kernel(const float* __restrict__ b_enc)
{
    __shared__ __align__(16) __half Ah[128][TP2];
    __shared__ __align__(16) __half Am[128][TP2];
    __shared__ __align__(16) __half Wh[128][TP2];
    __shared__ __align__(16) __half Wm[128][TP2];
    __shared__ __align__(16) float  stage[8][16 * SP];

    const int tid = threadIdx.x;
    const int wid = tid >> 5, lane = tid & 31;
    const int wm = wid >> 2, wn = wid & 3;     // warp tile: rows [wm*64,+64), cols [wn*32,+32)
    const int bm = blockIdx.x * 128;           // over B
    const int bn = blockIdx.y * 128;           // over F

    const int lm = tid >> 1, lq = (tid & 1) * 8;   // loader: row lm, halves [lq, lq+8)

    wmma::fragment<wmma::accumulator, 16, 16, 16, float> c[4][2];
#pragma unroll
    for (int mf = 0; mf < 4; mf++)
#pragma unroll
        for (int nf = 0; nf < 2; nf++)
            wmma::fill_fragment(c[mf][nf], 0.f);

    uint4 rxh, rxm, rwh, rwm;   // prefetch registers
    auto load_regs = [&](int k0) {
        size_t xo = (size_t)(bm + lm) * DDIM + k0 + lq;
        size_t wo = (size_t)(bn + lm) * DDIM + k0 + lq;
        rxh = *(const uint4*)(g_Xh + xo);
        rxm = *(const uint4*)(g_Xm + xo);
        rwh = *(const uint4*)(g_Wh + wo);
        rwm = *(const uint4*)(g_Wm + wo);
    };
    auto store_smem = [&]() {
        *(uint4*)&Ah[lm][lq] = rxh;
        *(uint4*)&Am[lm][lq] = rxm;
        *(uint4*)&Wh[lm][lq] = rwh;
        *(uint4*)&Wm[lm][lq] = rwm;
    };

    load_regs(0);
    for (int k0 = 0; k0 < DDIM; k0 += 16) {
        store_smem();
        __syncthreads();
        if (k0 + 16 < DDIM) load_regs(k0 + 16);   // overlap next loads with compute

        wmma::fragment<wmma::matrix_a, 16, 16, 16, __half, wmma::row_major> ah[4], am[4];
#pragma unroll
        for (int mf = 0; mf < 4; mf++) {
            wmma::load_matrix_sync(ah[mf], &Ah[wm * 64 + mf * 16][0], TP2);
            wmma::load_matrix_sync(am[mf], &Am[wm * 64 + mf * 16][0], TP2);
        }
#pragma unroll
        for (int nf = 0; nf < 2; nf++) {
            wmma::fragment<wmma::matrix_b, 16, 16, 16, __half, wmma::col_major> bh, bm2;
            wmma::load_matrix_sync(bh,  &Wh[wn * 32 + nf * 16][0], TP2);
            wmma::load_matrix_sync(bm2, &Wm[wn * 32 + nf * 16][0], TP2);
#pragma unroll
            for (int mf = 0; mf < 4; mf++) {
                wmma::mma_sync(c[mf][nf], ah[mf], bh,  c[mf][nf]);
                wmma::mma_sync(c[mf][nf], ah[mf], bm2, c[mf][nf]);
                wmma::mma_sync(c[mf][nf], am[mf], bh,  c[mf][nf]);
            }
        }
        __syncthreads();
    }

    // ---- epilogue (PROVEN R9) ----
    const float inv = 1.f / 4096.f;
    const int r2 = lane >> 1, cq = (lane & 1) * 8;
#pragma unroll
    for (int mf = 0; mf < 4; mf++) {
#pragma unroll
        for (int nf = 0; nf < 2; nf++) {
            wmma::store_matrix_sync(&stage[wid][0], c[mf][nf], SP, wmma::mem_row_major);
            __syncwarp();
            int grow = bm + wm * 64 + mf * 16 + r2;
            int gcol = bn + wn * 32 + nf * 16 + cq;
            float4 s0 = *(const float4*)(&stage[wid][r2 * SP + cq]);
            float4 s1 = *(const float4*)(&stage[wid][r2 * SP + cq + 4]);
            float4 o0, o1;
            o0.x = fmaxf(s0.x * inv + b_enc[gcol + 0], 0.f);
            o0.y = fmaxf(s0.y * inv + b_enc[gcol + 1], 0.f);
            o0.z = fmaxf(s0.z * inv + b_enc[gcol + 2], 0.f);
            o0.w = fmaxf(s0.w * inv + b_enc[gcol + 3], 0.f);
            o1.x = fmaxf(s1.x * inv + b_enc[gcol + 4], 0.f);
            o1.y = fmaxf(s1.y * inv + b_enc[gcol + 5], 0.f);
            o1.z = fmaxf(s1.z * inv + b_enc[gcol + 6], 0.f);
            o1.w = fmaxf(s1.w * inv + b_enc[gcol + 7], 0.f);
            *(float4*)(g_pre + (size_t)grow * FDIM + gcol)     = o0;
            *(float4*)(g_pre + (size_t)grow * FDIM + gcol + 4) = o1;
            __syncwarp();
        }
    }
}

// ---------------- exact top-64 radix select: 512 threads, 3 fused passes (PROVEN R10) ----------------
__global__ void topk_select_kernel(int which)
{
    const int b = blockIdx.x, t = threadIdx.x;   // 512 threads, 48 elems each
    const float* row = g_pre + (size_t)b * FDIM;
    __shared__ int   hist[2048];
    __shared__ int   sc[512];
    __shared__ int   sc2[512];
    __shared__ int   s_bstar, s_nabove, s_ncand;
    __shared__ int   cidx[1024];
    __shared__ float cval[1024];

    for (int i = t; i < 2048; i += 512) hist[i] = 0;
    __syncthreads();
    for (int j = 0; j < 48; j++) {
        float v = row[t + (j << 9)];
        if (v > 0.f) atomicAdd(&hist[__float_as_uint(v) >> 21], 1);
    }
    __syncthreads();
    {
        int s = 0;
#pragma unroll
        for (int i = 0; i < 4; i++) s += hist[t * 4 + i];
        sc[t] = s;
    }
    __syncthreads();
    if (t == 0) {
        int cum = 0, bstar = 0, nab = 0;
        bool found = false;
        for (int s = 511; s >= 0 && !found; s--) {
            int sv = sc[s];
            if (sv == 0) continue;
            if (cum + sv >= KTOP) {
                for (int bi = s * 4 + 3; bi >= s * 4; bi--) {
                    int h = hist[bi];
                    if (cum + h >= KTOP) { bstar = bi; nab = cum; found = true; break; }
                    cum += h;
                }
            } else cum += sv;
        }
        if (!found) { bstar = 0; nab = cum; }
        s_bstar = bstar; s_nabove = nab;
    }
    __syncthreads();
    const unsigned bstar = (unsigned)s_bstar;
    const int nabove = s_nabove;

    float* ov = ((which == 0) ? g_upvals : g_downvals) + b * KTOP;
    int*   oi = ((which == 0) ? g_upidx  : g_downidx)  + b * KTOP;

    int cnt = 0, ccnt = 0;
    for (int j = 0; j < 48; j++) {
        float v = row[t + (j << 9)];
        if (v > 0.f) {
            unsigned bin = __float_as_uint(v) >> 21;
            cnt  += (bin > bstar);
            ccnt += (bin == bstar);
        }
    }
    sc[t] = cnt; sc2[t] = ccnt;
    __syncthreads();
    for (int o = 1; o < 512; o <<= 1) {
        int v1 = (t >= o) ? sc[t - o] : 0;
        int v2 = (t >= o) ? sc2[t - o] : 0;
        __syncthreads();
        sc[t] += v1; sc2[t] += v2;
        __syncthreads();
    }
    if (t == 511) s_ncand = (sc2[511] < 1024) ? sc2[511] : 1024;

    {
        int pos = sc[t] - cnt, cpos = sc2[t] - ccnt;
        int left = cnt + ccnt;
        for (int j = 0; j < 48 && left > 0; j++) {
            int idx = t + (j << 9);
            float v = row[idx];
            if (v > 0.f) {
                unsigned bin = __float_as_uint(v) >> 21;
                if (bin > bstar) {
                    ov[pos] = v; oi[pos] = idx; pos++; left--;
                } else if (bin == bstar) {
                    if (cpos < 1024) { cidx[cpos] = idx; cval[cpos] = v; }
                    cpos++; left--;
                }
            }
        }
    }
    __syncthreads();

    if (t < 32) {
        const int need = KTOP - nabove;
        const int ncand = s_ncand;
        for (int r = 0; r < need; r++) {
            float bv = -1.f; int bidx = 0x7fffffff; int bslot = -1;
            for (int i = t; i < ncand; i += 32) {
                int ix = cidx[i];
                if (ix >= 0) {
                    float v = cval[i];
                    if (v > bv || (v == bv && ix < bidx)) { bv = v; bidx = ix; bslot = i; }
                }
            }
#pragma unroll
            for (int o = 16; o > 0; o >>= 1) {
                float v2 = __shfl_down_sync(0xffffffffu, bv, o);
                int   i2 = __shfl_down_sync(0xffffffffu, bidx, o);
                int   s2 = __shfl_down_sync(0xffffffffu, bslot, o);
                if (v2 > bv || (v2 == bv && i2 < bidx)) { bv = v2; bidx = i2; bslot = s2; }
            }
            bv = __shfl_sync(0xffffffffu, bv, 0);
            bidx = __shfl_sync(0xffffffffu, bidx, 0);
            bslot = __shfl_sync(0xffffffffu, bslot, 0);
            if (t == 0 && bslot >= 0) {
                ov[nabove + r] = bv; oi[nabove + r] = bidx; cidx[bslot] = -1;
            }
            __syncwarp();
        }
    }
}

// ---------------- contributions: approx_acts[b,kd] (PROVEN) ----------------
__global__ void contrib_kernel(const int* __restrict__ conn,
                               const float* __restrict__ W_enc_down)
{
    const int b = blockIdx.x;
    const int w = threadIdx.x >> 5, lane = threadIdx.x & 31;
    __shared__ int   s_ui[KTOP];
    __shared__ float s_uv[KTOP];
    if (threadIdx.x < KTOP) {
        s_ui[threadIdx.x] = g_upidx[b * KTOP + threadIdx.x];
        s_uv[threadIdx.x] = g_upvals[b * KTOP + threadIdx.x];
    }
    __syncthreads();

    for (int kd = w; kd < KTOP; kd += 8) {
        int fd = g_downidx[b * KTOP + kd];
        int ci = conn[(size_t)fd * CONN + lane];

        float partial = 0.f;
        bool loaded = false;
        float er[24];
        for (int ku = 0; ku < KTOP; ku++) {
            int fu = s_ui[ku];
            unsigned m = __ballot_sync(0xffffffffu, ci == fu);
            if (m) {
                if (!loaded) {
#pragma unroll
                    for (int i = 0; i < 24; i++)
                        er[i] = W_enc_down[(size_t)fd * DDIM + lane + i * 32];
                    loaded = true;
                }
                float cntf = (float)__popc(m);
                const float* up = g_WupT + (size_t)fu * DDIM + lane;
                float dot = 0.f;
#pragma unroll
                for (int i = 0; i < 24; i++) dot += er[i] * up[i * 32];
                partial += dot * cntf * s_uv[ku];
            }
        }
#pragma unroll
        for (int o = 16; o > 0; o >>= 1)
            partial += __shfl_down_sync(0xffffffffu, partial, o);
        if (lane == 0) g_approx[b * KTOP + kd] = partial;
    }
}

// ---------------- sparse decode (PROVEN) ----------------
__global__ void recon_kernel(int which, const float* __restrict__ b_dec, float* __restrict__ out)
{
    const int b = blockIdx.x;
    const int t = threadIdx.x;  // 256
    __shared__ float sv[KTOP];
    __shared__ int   si[KTOP];
    if (t < KTOP) {
        if (which == 0) { sv[t] = g_upvals[b * KTOP + t]; si[t] = g_upidx[b * KTOP + t]; }
        else            { sv[t] = g_approx[b * KTOP + t]; si[t] = g_downidx[b * KTOP + t]; }
    }
    __syncthreads();
    const float* WT = (which == 0) ? g_WupT : g_WdownT;

    float a0 = b_dec[t], a1 = b_dec[t + 256], a2 = b_dec[t + 512];
    for (int k = 0; k < KTOP; k++) {
        const float* p = WT + (size_t)si[k] * DDIM + t;
        float v = sv[k];
        a0 += v * p[0];
        a1 += v * p[256];
        a2 += v * p[512];
    }
    size_t o = (size_t)b * DDIM + t;
    out[o]       = a0;
    out[o + 256] = a1;
    out[o + 512] = a2;
}

// ---------------- launch ----------------
extern "C" void kernel_launch(void* const* d_in, const int* in_sizes, int n_in,
                              void* d_out, int out_size)
{
    (void)in_sizes; (void)n_in; (void)out_size;
    const float* x_up       = (const float*)d_in[0];
    const float* x_down     = (const float*)d_in[1];
    const float* W_enc_up   = (const float*)d_in[2];
    const float* b_enc_up   = (const float*)d_in[3];
    const float* W_dec_up   = (const float*)d_in[4];
    const float* b_dec_up   = (const float*)d_in[5];
    const float* W_enc_down = (const float*)d_in[6];
    const float* b_enc_down = (const float*)d_in[7];
    const float* W_dec_down = (const float*)d_in[8];
    const float* b_dec_down = (const float*)d_in[9];
    const int*   connections = (const int*)d_in[10];
    float* out = (float*)d_out;

    const int n8w = FDIM * DDIM / 8;   // 2359296
    const int n8x = B_TOK * DDIM / 8;  // 98304
    dim3 tb(32, 8);
    dim3 gemm_grid(B_TOK / 128, FDIM / 128);   // x: B tiles (8), y: F tiles (192)

    // ---- upstream ----
    split_w_kernel<<<n8w / 512, 512>>>(W_enc_up, n8w);
    split_x_kernel<<<n8x / 512, 512>>>(x_up, b_dec_up, n8x);
    gemm_wmma_kernel<<<gemm_grid, 256>>>(b_enc_up);
    topk_select_kernel<<<B_TOK, 512>>>(0);
    transpose_kernel<<<dim3(FDIM / 32, DDIM / 32), tb>>>(W_dec_up, 0);
    recon_kernel<<<B_TOK, 256>>>(0, b_dec_up, out);

    // ---- downstream ----
    split_w_kernel<<<n8w / 512, 512>>>(W_enc_down, n8w);
    split_x_kernel<<<n8x / 512, 512>>>(x_down, b_dec_down, n8x);
    gemm_wmma_kernel<<<gemm_grid, 256>>>(b_enc_down);
    topk_select_kernel<<<B_TOK, 512>>>(1);
    transpose_kernel<<<dim3(FDIM / 32, DDIM / 32), tb>>>(W_dec_down, 1);
    contrib_kernel<<<B_TOK, 256>>>(connections, W_enc_down);
    recon_kernel<<<B_TOK, 256>>>(1, b_dec_down, out + (size_t)B_TOK * DDIM);
}